// round 5
// baseline (speedup 1.0000x reference)
#include <cuda_runtime.h>
#include <math.h>

// Problem constants
#define Bb 2
#define Nn 2048
#define Dd 1024
#define Ee 8
#define Hh 2048
#define Kk 2
#define Tt (Bb*Nn)              // 4096 tokens

// GEMM tiling
#define BM 128
#define BN 128
#define BK 8
#define TM 8
#define TN 8

// ---------------- scratch (device globals; no allocations allowed) ----------
__device__ int   g_count[Ee];                 // tokens routed to each expert
__device__ float g_ent;                       // entropy accumulator
__device__ int   g_tok[Ee * Tt];              // token id at (expert, pos)
__device__ int   g_slot[Tt * Kk];             // e*Tt+pos per (token, k)
__device__ float g_gatev[Tt * Kk];            // softmaxed gate per (token, k)
__device__ int   g_eidx[Tt * Kk];             // expert id per (token, k)
__device__ float g_h[(size_t)Ee * Tt * Hh];   // hidden activations (268 MB)
__device__ float g_y[(size_t)Ee * Tt * Dd];   // expert outputs      (134 MB)

// ---------------- reset ------------------------------------------------------
__global__ void reset_kernel() {
    int i = threadIdx.x;
    if (i < Ee) g_count[i] = 0;
    if (i == 0) g_ent = 0.0f;
}

// ---------------- gating: one warp per token --------------------------------
__global__ void gate_kernel(const float* __restrict__ x,
                            const float* __restrict__ wg,
                            const float* __restrict__ bg) {
    int t    = (blockIdx.x * blockDim.x + threadIdx.x) >> 5;
    int lane = threadIdx.x & 31;
    if (t >= Tt) return;

    const float* xr = x + (size_t)t * Dd;
    float acc[Ee];
    #pragma unroll
    for (int e = 0; e < Ee; e++) acc[e] = 0.0f;

    for (int d = lane; d < Dd; d += 32) {
        float xv = xr[d];
        const float4* w4 = (const float4*)(wg + (size_t)d * Ee);
        float4 a = w4[0], b = w4[1];
        acc[0] += xv * a.x; acc[1] += xv * a.y; acc[2] += xv * a.z; acc[3] += xv * a.w;
        acc[4] += xv * b.x; acc[5] += xv * b.y; acc[6] += xv * b.z; acc[7] += xv * b.w;
    }
    #pragma unroll
    for (int e = 0; e < Ee; e++) {
        #pragma unroll
        for (int off = 16; off; off >>= 1)
            acc[e] += __shfl_xor_sync(0xffffffffu, acc[e], off);
    }

    if (lane == 0) {
        float best0 = -INFINITY, best1 = -INFINITY;
        int i0 = 0, i1 = 0;
        #pragma unroll
        for (int e = 0; e < Ee; e++) {
            float l = acc[e] + bg[e];
            if (l > best0)      { best1 = best0; i1 = i0; best0 = l; i0 = e; }
            else if (l > best1) { best1 = l; i1 = e; }
        }
        // softmax over the two selected logits
        float ex = expf(best1 - best0);          // <= 1
        float g0 = 1.0f / (1.0f + ex);
        float g1 = ex * g0;
        float ent = -(g0 * logf(fmaxf(g0, 1e-8f)) + g1 * logf(fmaxf(g1, 1e-8f)));
        atomicAdd(&g_ent, ent);

        int p0 = atomicAdd(&g_count[i0], 1);
        g_tok[i0 * Tt + p0]  = t;
        g_slot[t * Kk + 0]   = i0 * Tt + p0;
        g_gatev[t * Kk + 0]  = g0;
        g_eidx[t * Kk + 0]   = i0;

        int p1 = atomicAdd(&g_count[i1], 1);
        g_tok[i1 * Tt + p1]  = t;
        g_slot[t * Kk + 1]   = i1 * Tt + p1;
        g_gatev[t * Kk + 1]  = g1;
        g_eidx[t * Kk + 1]   = i1;
    }
}

// ---------------- FFN1: h = relu(X_e @ W1_e + b1_e) --------------------------
__global__ __launch_bounds__(256, 2)
void ffn1_kernel(const float* __restrict__ x,
                 const float* __restrict__ w1,
                 const float* __restrict__ b1) {
    int e   = blockIdx.z;
    int cnt = g_count[e];
    int m0  = blockIdx.y * BM;
    if (m0 >= cnt) return;
    int n0  = blockIdx.x * BN;

    __shared__ float As[BK][BM];
    __shared__ float Bs[BK][BN];
    __shared__ int   toks[BM];

    int tid = threadIdx.x;
    if (tid < BM) {
        int m = m0 + tid;
        toks[tid] = (m < cnt) ? g_tok[e * Tt + m] : -1;
    }
    __syncthreads();

    int arow = tid >> 1, akq = (tid & 1) * 4;   // A: 128 rows x 8 k, float4 each
    int bkr  = tid >> 5, bnq = (tid & 31) * 4;  // B: 8 k x 128 n
    int tx   = tid & 15, ty  = tid >> 4;
    int atok = toks[arow];

    const float* w1e = w1 + (size_t)e * Dd * Hh;

    float acc[TM][TN];
    #pragma unroll
    for (int i = 0; i < TM; i++)
        #pragma unroll
        for (int j = 0; j < TN; j++) acc[i][j] = 0.0f;

    for (int k0 = 0; k0 < Dd; k0 += BK) {
        float4 av = (atok >= 0)
            ? *(const float4*)(x + (size_t)atok * Dd + k0 + akq)
            : make_float4(0.f, 0.f, 0.f, 0.f);
        float4 bv = *(const float4*)(w1e + (size_t)(k0 + bkr) * Hh + n0 + bnq);
        __syncthreads();
        As[akq + 0][arow] = av.x; As[akq + 1][arow] = av.y;
        As[akq + 2][arow] = av.z; As[akq + 3][arow] = av.w;
        *(float4*)&Bs[bkr][bnq] = bv;
        __syncthreads();
        #pragma unroll
        for (int kk = 0; kk < BK; kk++) {
            float a[TM], b[TN];
            #pragma unroll
            for (int i = 0; i < TM; i++) a[i] = As[kk][ty * TM + i];
            #pragma unroll
            for (int j = 0; j < TN; j++) b[j] = Bs[kk][tx * TN + j];
            #pragma unroll
            for (int i = 0; i < TM; i++)
                #pragma unroll
                for (int j = 0; j < TN; j++) acc[i][j] += a[i] * b[j];
        }
    }

    float b1v[TN];
    #pragma unroll
    for (int j = 0; j < TN; j++)
        b1v[j] = b1[(size_t)e * Hh + n0 + tx * TN + j];

    #pragma unroll
    for (int i = 0; i < TM; i++) {
        int m = m0 + ty * TM + i;
        if (m >= cnt) continue;
        float4 v0, v1;
        v0.x = fmaxf(acc[i][0] + b1v[0], 0.f); v0.y = fmaxf(acc[i][1] + b1v[1], 0.f);
        v0.z = fmaxf(acc[i][2] + b1v[2], 0.f); v0.w = fmaxf(acc[i][3] + b1v[3], 0.f);
        v1.x = fmaxf(acc[i][4] + b1v[4], 0.f); v1.y = fmaxf(acc[i][5] + b1v[5], 0.f);
        v1.z = fmaxf(acc[i][6] + b1v[6], 0.f); v1.w = fmaxf(acc[i][7] + b1v[7], 0.f);
        float* hr = g_h + ((size_t)e * Tt + m) * Hh + n0 + tx * TN;
        ((float4*)hr)[0] = v0;
        ((float4*)hr)[1] = v1;
    }
}

// ---------------- FFN2: y = h_e @ W2_e ---------------------------------------
__global__ __launch_bounds__(256, 2)
void ffn2_kernel(const float* __restrict__ w2) {
    int e   = blockIdx.z;
    int cnt = g_count[e];
    int m0  = blockIdx.y * BM;
    if (m0 >= cnt) return;
    int n0  = blockIdx.x * BN;

    __shared__ float As[BK][BM];
    __shared__ float Bs[BK][BN];

    int tid  = threadIdx.x;
    int arow = tid >> 1, akq = (tid & 1) * 4;
    int bkr  = tid >> 5, bnq = (tid & 31) * 4;
    int tx   = tid & 15, ty  = tid >> 4;
    bool avalid = (m0 + arow) < cnt;
    const float* arp = g_h + ((size_t)e * Tt + m0 + arow) * Hh;
    const float* w2e = w2 + (size_t)e * Hh * Dd;

    float acc[TM][TN];
    #pragma unroll
    for (int i = 0; i < TM; i++)
        #pragma unroll
        for (int j = 0; j < TN; j++) acc[i][j] = 0.0f;

    for (int k0 = 0; k0 < Hh; k0 += BK) {
        float4 av = avalid ? *(const float4*)(arp + k0 + akq)
                           : make_float4(0.f, 0.f, 0.f, 0.f);
        float4 bv = *(const float4*)(w2e + (size_t)(k0 + bkr) * Dd + n0 + bnq);
        __syncthreads();
        As[akq + 0][arow] = av.x; As[akq + 1][arow] = av.y;
        As[akq + 2][arow] = av.z; As[akq + 3][arow] = av.w;
        *(float4*)&Bs[bkr][bnq] = bv;
        __syncthreads();
        #pragma unroll
        for (int kk = 0; kk < BK; kk++) {
            float a[TM], b[TN];
            #pragma unroll
            for (int i = 0; i < TM; i++) a[i] = As[kk][ty * TM + i];
            #pragma unroll
            for (int j = 0; j < TN; j++) b[j] = Bs[kk][tx * TN + j];
            #pragma unroll
            for (int i = 0; i < TM; i++)
                #pragma unroll
                for (int j = 0; j < TN; j++) acc[i][j] += a[i] * b[j];
        }
    }

    #pragma unroll
    for (int i = 0; i < TM; i++) {
        int m = m0 + ty * TM + i;
        if (m >= cnt) continue;
        float* yr = g_y + ((size_t)e * Tt + m) * Dd + n0 + tx * TN;
        float4 v0 = make_float4(acc[i][0], acc[i][1], acc[i][2], acc[i][3]);
        float4 v1 = make_float4(acc[i][4], acc[i][5], acc[i][6], acc[i][7]);
        ((float4*)yr)[0] = v0;
        ((float4*)yr)[1] = v1;
    }
}

// ---------------- combine: out[t] = g0*(y0+b2[e0]) + g1*(y1+b2[e1]) ----------
__global__ void combine_kernel(const float* __restrict__ b2,
                               float* __restrict__ out) {
    int t   = blockIdx.x;
    int tid = threadIdx.x;           // 256 threads * float4 = 1024 = Dd
    int s0 = g_slot[t * Kk + 0], s1 = g_slot[t * Kk + 1];
    float g0 = g_gatev[t * Kk + 0], g1 = g_gatev[t * Kk + 1];
    int e0 = g_eidx[t * Kk + 0], e1 = g_eidx[t * Kk + 1];

    const float4* y0 = (const float4*)(g_y + (size_t)s0 * Dd);
    const float4* y1 = (const float4*)(g_y + (size_t)s1 * Dd);
    const float4* c0 = (const float4*)(b2 + (size_t)e0 * Dd);
    const float4* c1 = (const float4*)(b2 + (size_t)e1 * Dd);
    float4* o = (float4*)(out + (size_t)t * Dd);

    float4 a = y0[tid], b = y1[tid], p = c0[tid], q = c1[tid];
    float4 r;
    r.x = g0 * (a.x + p.x) + g1 * (b.x + q.x);
    r.y = g0 * (a.y + p.y) + g1 * (b.y + q.y);
    r.z = g0 * (a.z + p.z) + g1 * (b.z + q.z);
    r.w = g0 * (a.w + p.w) + g1 * (b.w + q.w);
    o[tid] = r;
}

// ---------------- entropy scalar ---------------------------------------------
__global__ void ent_kernel(float* __restrict__ out, int out_size) {
    if (out_size > Tt * Dd)
        out[Tt * Dd] = g_ent / (float)Tt;
}

// ---------------- launch ------------------------------------------------------
extern "C" void kernel_launch(void* const* d_in, const int* in_sizes, int n_in,
                              void* d_out, int out_size) {
    const float* x  = (const float*)d_in[0];
    const float* wg = (const float*)d_in[1];
    const float* bg = (const float*)d_in[2];
    const float* w1 = (const float*)d_in[3];
    const float* b1 = (const float*)d_in[4];
    const float* w2 = (const float*)d_in[5];
    const float* b2 = (const float*)d_in[6];
    float* out = (float*)d_out;

    reset_kernel<<<1, 32>>>();
    gate_kernel<<<Tt / 8, 256>>>(x, wg, bg);          // 8 warps/block, 1 warp/token

    dim3 grid1(Hh / BN, Tt / BM, Ee);                 // (16, 32, 8)
    ffn1_kernel<<<grid1, 256>>>(x, w1, b1);

    dim3 grid2(Dd / BN, Tt / BM, Ee);                 // (8, 32, 8)
    ffn2_kernel<<<grid2, 256>>>(w2);

    combine_kernel<<<Tt, 256>>>(b2, out);
    ent_kernel<<<1, 1>>>(out, out_size);
}

// round 7
// speedup vs baseline: 1.7805x; 1.7805x over previous
#include <cuda_runtime.h>
#include <cuda_bf16.h>
#include <math.h>
#include <stdint.h>

typedef __nv_bfloat16 bf16;

// Problem constants
#define Bb 2
#define Nn 2048
#define Dd 1024
#define Ee 8
#define Hh 2048
#define Kk 2
#define Tt (Bb*Nn)              // 4096 tokens
#define SLOTS (Tt*Kk)           // 8192 (token, expert) assignments

// ---------------- routing state ----------------------------------------------
__device__ int   g_count[Ee];
__device__ int   g_off[Ee];                   // exclusive prefix of counts
__device__ float g_ent;
__device__ int   g_tok[Ee * Tt];              // token id at (expert, pos)
__device__ int   g_pos[Tt * Kk];              // pos within expert bucket
__device__ int   g_eidx[Tt * Kk];             // expert id
__device__ float g_gatev[Tt * Kk];            // softmaxed gate

// ---------------- bf16 split planes ------------------------------------------
__device__ bf16  g_xh[(size_t)Tt * Dd],      g_xl[(size_t)Tt * Dd];
__device__ bf16  g_w1h[(size_t)Ee * Hh * Dd], g_w1l[(size_t)Ee * Hh * Dd]; // [E][H][D]
__device__ bf16  g_w2h[(size_t)Ee * Dd * Hh], g_w2l[(size_t)Ee * Dd * Hh]; // [E][D][H]
__device__ bf16  g_hh[(size_t)SLOTS * Hh],   g_hl[(size_t)SLOTS * Hh];     // hidden (compacted)
__device__ float g_y[(size_t)SLOTS * Dd];                                  // expert outputs

// ============================ PTX helpers ====================================
__device__ __forceinline__ uint32_t smem_u32(const void* p) {
    uint32_t a;
    asm("{ .reg .u64 t; cvta.to.shared.u64 t, %1; cvt.u32.u64 %0, t; }"
        : "=r"(a) : "l"(p));
    return a;
}
__device__ __forceinline__ void cp16(uint32_t dst, const void* src, int sz) {
    asm volatile("cp.async.cg.shared.global [%0], [%1], 16, %2;"
                 :: "r"(dst), "l"(src), "r"(sz) : "memory");
}
__device__ __forceinline__ void cp_commit() {
    asm volatile("cp.async.commit_group;" ::: "memory");
}
__device__ __forceinline__ void cp_wait1() {
    asm volatile("cp.async.wait_group 1;" ::: "memory");
}
__device__ __forceinline__ void ldsm4(uint32_t* r, uint32_t addr) {
    asm volatile("ldmatrix.sync.aligned.m8n8.x4.shared.b16 {%0,%1,%2,%3}, [%4];"
                 : "=r"(r[0]), "=r"(r[1]), "=r"(r[2]), "=r"(r[3]) : "r"(addr));
}
__device__ __forceinline__ void mma16816(float* c, const uint32_t* a, const uint32_t* b) {
    asm volatile(
        "mma.sync.aligned.m16n8k16.row.col.f32.bf16.bf16.f32 "
        "{%0,%1,%2,%3}, {%4,%5,%6,%7}, {%8,%9}, {%0,%1,%2,%3};"
        : "+f"(c[0]), "+f"(c[1]), "+f"(c[2]), "+f"(c[3])
        : "r"(a[0]), "r"(a[1]), "r"(a[2]), "r"(a[3]), "r"(b[0]), "r"(b[1]));
}

// smem tile: 128 rows x 8 chunks of 16B (64 bf16), XOR-swizzled
__device__ __forceinline__ uint32_t sw_off(int row, int ch) {
    return (uint32_t)((row * 8 + (ch ^ (row & 7))) << 4);
}

// dynamic smem layout for MMA kernels:
//  [0,512)   toks[128]
//  [1024 + st*32768)        A stage st (16KB)
//  [1024 + st*32768 + 16384) B stage st (16KB)
#define NSTAGE 3
#define SM_A(st) (1024 + (st) * 32768)
#define SM_B(st) (1024 + (st) * 32768 + 16384)
#define MMA_SMEM_BYTES (1024 + NSTAGE * 32768)   // 99328

// ---------------- reset / offsets --------------------------------------------
__global__ void reset_kernel() {
    int i = threadIdx.x;
    if (i < Ee) g_count[i] = 0;
    if (i == 0) g_ent = 0.0f;
}
__global__ void offs_kernel() {
    if (threadIdx.x == 0) {
        int a = 0;
        #pragma unroll
        for (int e = 0; e < Ee; e++) { g_off[e] = a; a += g_count[e]; }
    }
}

// ---------------- gating: one warp per token ---------------------------------
__global__ void gate_kernel(const float* __restrict__ x,
                            const float* __restrict__ wg,
                            const float* __restrict__ bg) {
    int t    = (blockIdx.x * blockDim.x + threadIdx.x) >> 5;
    int lane = threadIdx.x & 31;
    if (t >= Tt) return;

    const float* xr = x + (size_t)t * Dd;
    float acc[Ee];
    #pragma unroll
    for (int e = 0; e < Ee; e++) acc[e] = 0.0f;

    for (int d = lane; d < Dd; d += 32) {
        float xv = xr[d];
        const float4* w4 = (const float4*)(wg + (size_t)d * Ee);
        float4 a = w4[0], b = w4[1];
        acc[0] += xv * a.x; acc[1] += xv * a.y; acc[2] += xv * a.z; acc[3] += xv * a.w;
        acc[4] += xv * b.x; acc[5] += xv * b.y; acc[6] += xv * b.z; acc[7] += xv * b.w;
    }
    #pragma unroll
    for (int e = 0; e < Ee; e++) {
        #pragma unroll
        for (int off = 16; off; off >>= 1)
            acc[e] += __shfl_xor_sync(0xffffffffu, acc[e], off);
    }

    if (lane == 0) {
        float best0 = -INFINITY, best1 = -INFINITY;
        int i0 = 0, i1 = 0;
        #pragma unroll
        for (int e = 0; e < Ee; e++) {
            float l = acc[e] + bg[e];
            if (l > best0)      { best1 = best0; i1 = i0; best0 = l; i0 = e; }
            else if (l > best1) { best1 = l; i1 = e; }
        }
        float ex = expf(best1 - best0);
        float g0 = 1.0f / (1.0f + ex);
        float g1 = ex * g0;
        float ent = -(g0 * logf(fmaxf(g0, 1e-8f)) + g1 * logf(fmaxf(g1, 1e-8f)));
        atomicAdd(&g_ent, ent);

        int p0 = atomicAdd(&g_count[i0], 1);
        g_tok[i0 * Tt + p0] = t;
        g_pos[t * Kk + 0]   = p0;
        g_gatev[t * Kk + 0] = g0;
        g_eidx[t * Kk + 0]  = i0;

        int p1 = atomicAdd(&g_count[i1], 1);
        g_tok[i1 * Tt + p1] = t;
        g_pos[t * Kk + 1]   = p1;
        g_gatev[t * Kk + 1] = g1;
        g_eidx[t * Kk + 1]  = i1;
    }
}

// ---------------- conversions ------------------------------------------------
__device__ __forceinline__ unsigned pack2(float a, float b) {
    bf16 ha = __float2bfloat16(a), hb = __float2bfloat16(b);
    return (unsigned)__bfloat16_as_ushort(ha)
         | ((unsigned)__bfloat16_as_ushort(hb) << 16);
}

__global__ void conv_x_kernel(const float* __restrict__ x) {
    int i = blockIdx.x * blockDim.x + threadIdx.x;       // Tt*Dd/4 threads
    float4 v = ((const float4*)x)[i];
    float hx = __bfloat162float(__float2bfloat16(v.x));
    float hy = __bfloat162float(__float2bfloat16(v.y));
    float hz = __bfloat162float(__float2bfloat16(v.z));
    float hw = __bfloat162float(__float2bfloat16(v.w));
    ((uint2*)g_xh)[i] = make_uint2(pack2(v.x, v.y), pack2(v.z, v.w));
    ((uint2*)g_xl)[i] = make_uint2(pack2(v.x - hx, v.y - hy), pack2(v.z - hz, v.w - hw));
}

// transpose + split:  in [E][R][C] -> out [E][C][R]
__device__ __forceinline__ void transpose_conv_body(
    const float* __restrict__ in, bf16* __restrict__ oh, bf16* __restrict__ ol,
    int R, int C) {
    __shared__ float ts[32][33];
    int e  = blockIdx.z;
    int r0 = blockIdx.y * 32, c0 = blockIdx.x * 32;
    int tx = threadIdx.x, ty = threadIdx.y;
    const float* ip = in + (size_t)e * R * C;
    #pragma unroll
    for (int i = 0; i < 4; i++)
        ts[ty + 8 * i][tx] = ip[(size_t)(r0 + ty + 8 * i) * C + (c0 + tx)];
    __syncthreads();
    bf16* ohp = oh + (size_t)e * C * R;
    bf16* olp = ol + (size_t)e * C * R;
    #pragma unroll
    for (int i = 0; i < 4; i++) {
        float v = ts[tx][ty + 8 * i];
        bf16 h = __float2bfloat16(v);
        size_t o = (size_t)(c0 + ty + 8 * i) * R + (r0 + tx);
        ohp[o] = h;
        olp[o] = __float2bfloat16(v - __bfloat162float(h));
    }
}
__global__ void conv_w1_kernel(const float* __restrict__ w1) {
    transpose_conv_body(w1, g_w1h, g_w1l, Dd, Hh);
}
__global__ void conv_w2_kernel(const float* __restrict__ w2) {
    transpose_conv_body(w2, g_w2h, g_w2l, Hh, Dd);
}

// ---------------- HMMA GEMM: 128x128 tile, BK=64, 3-stage cp.async -----------
// FFN1: C[cnt,H] = Xg[cnt,D] @ W1t[H,D]^T  (+b1, relu -> bf16 hi/lo planes)
// FFN2: C[cnt,D] = H [cnt,H] @ W2t[D,H]^T  (-> fp32 y)
// 3 K-segments: hi*hi, hi*lo(B), lo(A)*hi  => fp32-accurate to ~1e-5.
template <bool FFN1>
__global__ __launch_bounds__(256)
void moe_mma_kernel(const float* __restrict__ b1) {
    constexpr int KTOT = FFN1 ? Dd : Hh;
    constexpr int NCH  = KTOT / 64;
    constexpr int NSTG = 3 * NCH;

    int e   = blockIdx.z;
    int cnt = g_count[e];
    int m0  = blockIdx.y * 128;
    if (m0 >= cnt) return;
    int n0  = blockIdx.x * 128;
    int off = g_off[e];

    extern __shared__ __align__(1024) char smem[];
    uint32_t sbase = smem_u32(smem);
    int tid = threadIdx.x, wid = tid >> 5, lid = tid & 31;
    int wr = wid & 3, wc = wid >> 2;          // warp tile: rows wr*32, cols wc*64

    int* toks = (int*)smem;
    if (FFN1 && tid < 128) {
        int m = m0 + tid;
        toks[tid] = (m < cnt) ? g_tok[e * Tt + m] : -1;
    }
    __syncthreads();

    const bf16* APl[3];
    const bf16* BPl[3];
    if (FFN1) {
        APl[0] = g_xh;  APl[1] = g_xh;  APl[2] = g_xl;
        BPl[0] = g_w1h + (size_t)e * (size_t)Hh * Dd;
        BPl[1] = g_w1l + (size_t)e * (size_t)Hh * Dd;
        BPl[2] = BPl[0];
    } else {
        APl[0] = g_hh;  APl[1] = g_hh;  APl[2] = g_hl;
        BPl[0] = g_w2h + (size_t)e * (size_t)Dd * Hh;
        BPl[1] = g_w2l + (size_t)e * (size_t)Dd * Hh;
        BPl[2] = BPl[0];
    }

    // per-thread load slots: 4 chunks for A, 4 for B (1024 chunks each tile)
    int lrowA[4], lchA[4];
    #pragma unroll
    for (int i = 0; i < 4; i++) {
        int idx = tid + i * 256;
        lrowA[i] = idx >> 3; lchA[i] = idx & 7;
    }

    auto load_stage = [&](int s, int st) {
        int seg = s / NCH;
        int k0  = (s - seg * NCH) * 64;
        const bf16* ap = APl[seg];
        const bf16* bp = BPl[seg];
        #pragma unroll
        for (int i = 0; i < 4; i++) {
            int row = lrowA[i], ch = lchA[i];
            uint32_t dst = sbase + SM_A(st) + sw_off(row, ch);
            const bf16* src;
            int sz = 16;
            if (FFN1) {
                int tok = toks[row];
                src = (tok >= 0) ? ap + (size_t)tok * KTOT + k0 + ch * 8 : ap;
                if (tok < 0) sz = 0;
            } else {
                int m = m0 + row;
                src = (m < cnt) ? ap + (size_t)(off + m) * KTOT + k0 + ch * 8 : ap;
                if (m >= cnt) sz = 0;
            }
            cp16(dst, src, sz);
        }
        #pragma unroll
        for (int i = 0; i < 4; i++) {
            int row = lrowA[i], ch = lchA[i];
            uint32_t dst = sbase + SM_B(st) + sw_off(row, ch);
            cp16(dst, bp + (size_t)(n0 + row) * KTOT + k0 + ch * 8, 16);
        }
        cp_commit();
    };

    float acc[2][8][4];
    #pragma unroll
    for (int i = 0; i < 2; i++)
        #pragma unroll
        for (int j = 0; j < 8; j++)
            #pragma unroll
            for (int q = 0; q < 4; q++) acc[i][j][q] = 0.0f;

    load_stage(0, 0);
    load_stage(1, 1);

    for (int s = 0; s < NSTG; s++) {
        int st = s % NSTAGE;
        cp_wait1();
        __syncthreads();                       // stage s ready; stage (s-1) consumed
        if (s + 2 < NSTG) load_stage(s + 2, (s + 2) % NSTAGE);

        uint32_t abase = sbase + SM_A(st);
        uint32_t bbase = sbase + SM_B(st);
        #pragma unroll
        for (int kk = 0; kk < 4; kk++) {
            uint32_t afr[2][4];
            #pragma unroll
            for (int i = 0; i < 2; i++) {
                int row = wr * 32 + i * 16 + (lid & 15);
                int ch  = kk * 2 + (lid >> 4);
                ldsm4(afr[i], abase + sw_off(row, ch));
            }
            uint32_t bfr[8][2];
            #pragma unroll
            for (int j2 = 0; j2 < 4; j2++) {
                int row = wc * 64 + j2 * 16 + (lid & 7) + ((lid >> 4) << 3);
                int ch  = kk * 2 + ((lid >> 3) & 1);
                uint32_t r[4];
                ldsm4(r, bbase + sw_off(row, ch));
                bfr[j2 * 2][0] = r[0]; bfr[j2 * 2][1] = r[1];
                bfr[j2 * 2 + 1][0] = r[2]; bfr[j2 * 2 + 1][1] = r[3];
            }
            #pragma unroll
            for (int i = 0; i < 2; i++)
                #pragma unroll
                for (int j = 0; j < 8; j++)
                    mma16816(acc[i][j], afr[i], bfr[j]);
        }
    }

    // -------- epilogue (register accumulators) ------------------------------
    #pragma unroll
    for (int i = 0; i < 2; i++) {
        #pragma unroll
        for (int rh = 0; rh < 2; rh++) {
            int m = m0 + wr * 32 + i * 16 + rh * 8 + (lid >> 2);
            if (m >= cnt) continue;
            #pragma unroll
            for (int j = 0; j < 8; j++) {
                int n = n0 + wc * 64 + j * 8 + (lid & 3) * 2;
                float v0 = acc[i][j][rh * 2 + 0];
                float v1 = acc[i][j][rh * 2 + 1];
                if (FFN1) {
                    const float* b1p = b1 + (size_t)e * Hh + n;
                    v0 = fmaxf(v0 + b1p[0], 0.f);
                    v1 = fmaxf(v1 + b1p[1], 0.f);
                    float h0 = __bfloat162float(__float2bfloat16(v0));
                    float h1 = __bfloat162float(__float2bfloat16(v1));
                    size_t base = (size_t)(off + m) * Hh + n;
                    *(unsigned*)(g_hh + base) = pack2(v0, v1);
                    *(unsigned*)(g_hl + base) = pack2(v0 - h0, v1 - h1);
                } else {
                    size_t base = (size_t)(off + m) * Dd + n;
                    *(float2*)(g_y + base) = make_float2(v0, v1);
                }
            }
        }
    }
}

// ---------------- combine: out[t] = g0*(y0+b2[e0]) + g1*(y1+b2[e1]) ----------
__global__ void combine_kernel(const float* __restrict__ b2,
                               float* __restrict__ out) {
    int t   = blockIdx.x;
    int tid = threadIdx.x;                    // 256 threads * float4 = 1024 = Dd
    int e0 = g_eidx[t * Kk + 0], e1 = g_eidx[t * Kk + 1];
    int s0 = g_off[e0] + g_pos[t * Kk + 0];
    int s1 = g_off[e1] + g_pos[t * Kk + 1];
    float g0 = g_gatev[t * Kk + 0], g1 = g_gatev[t * Kk + 1];

    const float4* y0 = (const float4*)(g_y + (size_t)s0 * Dd);
    const float4* y1 = (const float4*)(g_y + (size_t)s1 * Dd);
    const float4* c0 = (const float4*)(b2 + (size_t)e0 * Dd);
    const float4* c1 = (const float4*)(b2 + (size_t)e1 * Dd);
    float4* o = (float4*)(out + (size_t)t * Dd);

    float4 a = y0[tid], b = y1[tid], p = c0[tid], q = c1[tid];
    float4 r;
    r.x = g0 * (a.x + p.x) + g1 * (b.x + q.x);
    r.y = g0 * (a.y + p.y) + g1 * (b.y + q.y);
    r.z = g0 * (a.z + p.z) + g1 * (b.z + q.z);
    r.w = g0 * (a.w + p.w) + g1 * (b.w + q.w);
    o[tid] = r;
}

__global__ void ent_kernel(float* __restrict__ out, int out_size) {
    if (out_size > Tt * Dd)
        out[Tt * Dd] = g_ent / (float)Tt;
}

// ---------------- launch ------------------------------------------------------
extern "C" void kernel_launch(void* const* d_in, const int* in_sizes, int n_in,
                              void* d_out, int out_size) {
    const float* x  = (const float*)d_in[0];
    const float* wg = (const float*)d_in[1];
    const float* bg = (const float*)d_in[2];
    const float* w1 = (const float*)d_in[3];
    const float* b1 = (const float*)d_in[4];
    const float* w2 = (const float*)d_in[5];
    const float* b2 = (const float*)d_in[6];
    float* out = (float*)d_out;

    cudaFuncSetAttribute(moe_mma_kernel<true>,
                         cudaFuncAttributeMaxDynamicSharedMemorySize, MMA_SMEM_BYTES);
    cudaFuncSetAttribute(moe_mma_kernel<false>,
                         cudaFuncAttributeMaxDynamicSharedMemorySize, MMA_SMEM_BYTES);

    reset_kernel<<<1, 32>>>();
    gate_kernel<<<Tt / 8, 256>>>(x, wg, bg);
    offs_kernel<<<1, 32>>>();

    conv_x_kernel<<<(Tt * Dd / 4) / 256, 256>>>(x);
    conv_w1_kernel<<<dim3(Hh / 32, Dd / 32, Ee), dim3(32, 8)>>>(w1);
    conv_w2_kernel<<<dim3(Dd / 32, Hh / 32, Ee), dim3(32, 8)>>>(w2);

    moe_mma_kernel<true ><<<dim3(Hh / 128, Tt / 128, Ee), 256, MMA_SMEM_BYTES>>>(b1);
    moe_mma_kernel<false><<<dim3(Dd / 128, Tt / 128, Ee), 256, MMA_SMEM_BYTES>>>(b1);

    combine_kernel<<<Tt, 256>>>(b2, out);
    ent_kernel<<<1, 1>>>(out, out_size);
}

// round 8
// speedup vs baseline: 2.7967x; 1.5708x over previous
#include <cuda_runtime.h>
#include <cuda_bf16.h>
#include <math.h>
#include <stdint.h>

typedef __nv_bfloat16 bf16;

// Problem constants
#define Bb 2
#define Nn 2048
#define Dd 1024
#define Ee 8
#define Hh 2048
#define Kk 2
#define Tt (Bb*Nn)              // 4096 tokens
#define SLOTS (Tt*Kk)           // 8192 (token, expert) assignments

// ---------------- routing state ----------------------------------------------
__device__ int   g_count[Ee];
__device__ int   g_off[Ee];                   // exclusive prefix of counts
__device__ float g_ent;
__device__ int   g_tok[Ee * Tt];              // token id at (expert, pos)
__device__ int   g_pos[Tt * Kk];              // pos within expert bucket
__device__ int   g_eidx[Tt * Kk];             // expert id
__device__ float g_gatev[Tt * Kk];            // softmaxed gate

// ---------------- bf16 split planes ------------------------------------------
__device__ bf16  g_xh[(size_t)Tt * Dd],      g_xl[(size_t)Tt * Dd];
__device__ bf16  g_w1h[(size_t)Ee * Hh * Dd], g_w1l[(size_t)Ee * Hh * Dd]; // [E][H][D]
__device__ bf16  g_w2h[(size_t)Ee * Dd * Hh], g_w2l[(size_t)Ee * Dd * Hh]; // [E][D][H]
__device__ bf16  g_hh[(size_t)SLOTS * Hh],   g_hl[(size_t)SLOTS * Hh];     // hidden (compacted)
__device__ float g_y[(size_t)SLOTS * Dd];                                  // expert outputs

// ============================ PTX helpers ====================================
__device__ __forceinline__ uint32_t smem_u32(const void* p) {
    uint32_t a;
    asm("{ .reg .u64 t; cvta.to.shared.u64 t, %1; cvt.u32.u64 %0, t; }"
        : "=r"(a) : "l"(p));
    return a;
}
__device__ __forceinline__ void cp16(uint32_t dst, const void* src, int sz) {
    asm volatile("cp.async.cg.shared.global [%0], [%1], 16, %2;"
                 :: "r"(dst), "l"(src), "r"(sz) : "memory");
}
__device__ __forceinline__ void cp_commit() {
    asm volatile("cp.async.commit_group;" ::: "memory");
}
__device__ __forceinline__ void cp_wait1() {
    asm volatile("cp.async.wait_group 1;" ::: "memory");
}
__device__ __forceinline__ void ldsm4(uint32_t* r, uint32_t addr) {
    asm volatile("ldmatrix.sync.aligned.m8n8.x4.shared.b16 {%0,%1,%2,%3}, [%4];"
                 : "=r"(r[0]), "=r"(r[1]), "=r"(r[2]), "=r"(r[3]) : "r"(addr));
}
__device__ __forceinline__ void mma16816(float* c, const uint32_t* a, const uint32_t* b) {
    asm volatile(
        "mma.sync.aligned.m16n8k16.row.col.f32.bf16.bf16.f32 "
        "{%0,%1,%2,%3}, {%4,%5,%6,%7}, {%8,%9}, {%0,%1,%2,%3};"
        : "+f"(c[0]), "+f"(c[1]), "+f"(c[2]), "+f"(c[3])
        : "r"(a[0]), "r"(a[1]), "r"(a[2]), "r"(a[3]), "r"(b[0]), "r"(b[1]));
}

// smem tile: rows x 8 chunks of 16B (64 bf16 per row), XOR-swizzled
__device__ __forceinline__ uint32_t sw_off(int row, int ch) {
    return (uint32_t)((row * 8 + (ch ^ (row & 7))) << 4);
}

// dynamic smem layout for MMA kernels:
//  [0,512)    toks[128]
//  A stages:  3 x 16KB  (128 rows x 64 bf16)
//  B stages:  3 x 32KB  (256 rows x 64 bf16)
#define NSTAGE 3
#define SM_A(st) (1024 + (st) * 16384)
#define SM_B(st) (1024 + 3 * 16384 + (st) * 32768)
#define MMA_SMEM_BYTES (1024 + 3 * 16384 + 3 * 32768)   // 148480

// ---------------- reset / offsets --------------------------------------------
__global__ void reset_kernel() {
    int i = threadIdx.x;
    if (i < Ee) g_count[i] = 0;
    if (i == 0) g_ent = 0.0f;
}
__global__ void offs_kernel() {
    if (threadIdx.x == 0) {
        int a = 0;
        #pragma unroll
        for (int e = 0; e < Ee; e++) { g_off[e] = a; a += g_count[e]; }
    }
}

// ---------------- gating: one warp per token ---------------------------------
__global__ void gate_kernel(const float* __restrict__ x,
                            const float* __restrict__ wg,
                            const float* __restrict__ bg) {
    int t    = (blockIdx.x * blockDim.x + threadIdx.x) >> 5;
    int lane = threadIdx.x & 31;
    if (t >= Tt) return;

    const float* xr = x + (size_t)t * Dd;
    float acc[Ee];
    #pragma unroll
    for (int e = 0; e < Ee; e++) acc[e] = 0.0f;

    for (int d = lane; d < Dd; d += 32) {
        float xv = xr[d];
        const float4* w4 = (const float4*)(wg + (size_t)d * Ee);
        float4 a = w4[0], b = w4[1];
        acc[0] += xv * a.x; acc[1] += xv * a.y; acc[2] += xv * a.z; acc[3] += xv * a.w;
        acc[4] += xv * b.x; acc[5] += xv * b.y; acc[6] += xv * b.z; acc[7] += xv * b.w;
    }
    #pragma unroll
    for (int e = 0; e < Ee; e++) {
        #pragma unroll
        for (int off = 16; off; off >>= 1)
            acc[e] += __shfl_xor_sync(0xffffffffu, acc[e], off);
    }

    if (lane == 0) {
        float best0 = -INFINITY, best1 = -INFINITY;
        int i0 = 0, i1 = 0;
        #pragma unroll
        for (int e = 0; e < Ee; e++) {
            float l = acc[e] + bg[e];
            if (l > best0)      { best1 = best0; i1 = i0; best0 = l; i0 = e; }
            else if (l > best1) { best1 = l; i1 = e; }
        }
        float ex = expf(best1 - best0);
        float g0 = 1.0f / (1.0f + ex);
        float g1 = ex * g0;
        float ent = -(g0 * logf(fmaxf(g0, 1e-8f)) + g1 * logf(fmaxf(g1, 1e-8f)));
        atomicAdd(&g_ent, ent);

        int p0 = atomicAdd(&g_count[i0], 1);
        g_tok[i0 * Tt + p0] = t;
        g_pos[t * Kk + 0]   = p0;
        g_gatev[t * Kk + 0] = g0;
        g_eidx[t * Kk + 0]  = i0;

        int p1 = atomicAdd(&g_count[i1], 1);
        g_tok[i1 * Tt + p1] = t;
        g_pos[t * Kk + 1]   = p1;
        g_gatev[t * Kk + 1] = g1;
        g_eidx[t * Kk + 1]  = i1;
    }
}

// ---------------- conversions ------------------------------------------------
__device__ __forceinline__ unsigned pack2(float a, float b) {
    bf16 ha = __float2bfloat16(a), hb = __float2bfloat16(b);
    return (unsigned)__bfloat16_as_ushort(ha)
         | ((unsigned)__bfloat16_as_ushort(hb) << 16);
}

__global__ void conv_x_kernel(const float* __restrict__ x) {
    int i = blockIdx.x * blockDim.x + threadIdx.x;       // Tt*Dd/4 threads
    float4 v = ((const float4*)x)[i];
    float hx = __bfloat162float(__float2bfloat16(v.x));
    float hy = __bfloat162float(__float2bfloat16(v.y));
    float hz = __bfloat162float(__float2bfloat16(v.z));
    float hw = __bfloat162float(__float2bfloat16(v.w));
    ((uint2*)g_xh)[i] = make_uint2(pack2(v.x, v.y), pack2(v.z, v.w));
    ((uint2*)g_xl)[i] = make_uint2(pack2(v.x - hx, v.y - hy), pack2(v.z - hz, v.w - hw));
}

// transpose + split:  in [E][R][C] -> out [E][C][R]
__device__ __forceinline__ void transpose_conv_body(
    const float* __restrict__ in, bf16* __restrict__ oh, bf16* __restrict__ ol,
    int R, int C) {
    __shared__ float ts[32][33];
    int e  = blockIdx.z;
    int r0 = blockIdx.y * 32, c0 = blockIdx.x * 32;
    int tx = threadIdx.x, ty = threadIdx.y;
    const float* ip = in + (size_t)e * R * C;
    #pragma unroll
    for (int i = 0; i < 4; i++)
        ts[ty + 8 * i][tx] = ip[(size_t)(r0 + ty + 8 * i) * C + (c0 + tx)];
    __syncthreads();
    bf16* ohp = oh + (size_t)e * C * R;
    bf16* olp = ol + (size_t)e * C * R;
    #pragma unroll
    for (int i = 0; i < 4; i++) {
        float v = ts[tx][ty + 8 * i];
        bf16 h = __float2bfloat16(v);
        size_t o = (size_t)(c0 + ty + 8 * i) * R + (r0 + tx);
        ohp[o] = h;
        olp[o] = __float2bfloat16(v - __bfloat162float(h));
    }
}
__global__ void conv_w1_kernel(const float* __restrict__ w1) {
    transpose_conv_body(w1, g_w1h, g_w1l, Dd, Hh);
}
__global__ void conv_w2_kernel(const float* __restrict__ w2) {
    transpose_conv_body(w2, g_w2h, g_w2l, Hh, Dd);
}

// ---------------- HMMA GEMM: 128x256 tile, BK=64, 3-stage cp.async -----------
// FFN1: C[cnt,H] = Xg[cnt,D] @ W1t[H,D]^T  (+b1, relu -> bf16 hi/lo planes)
// FFN2: C[cnt,D] = H [cnt,H] @ W2t[D,H]^T  (-> fp32 y)
// 3 K-segments: hi*hi, hi*lo(B), lo(A)*hi  => fp32-accurate to ~1e-5.
// 8 warps, warp tile 32(m) x 128(n).
template <bool FFN1>
__global__ __launch_bounds__(256, 1)
void moe_mma_kernel(const float* __restrict__ b1) {
    constexpr int KTOT = FFN1 ? Dd : Hh;
    constexpr int NCH  = KTOT / 64;
    constexpr int NSTG = 3 * NCH;

    int e   = blockIdx.z;
    int cnt = g_count[e];
    int m0  = blockIdx.y * 128;
    if (m0 >= cnt) return;
    int n0  = blockIdx.x * 256;
    int off = g_off[e];

    extern __shared__ __align__(1024) char smem[];
    uint32_t sbase = smem_u32(smem);
    int tid = threadIdx.x, wid = tid >> 5, lid = tid & 31;
    int wr = wid & 3, wc = wid >> 2;          // warp tile: rows wr*32, cols wc*128

    int* toks = (int*)smem;
    if (FFN1 && tid < 128) {
        int m = m0 + tid;
        toks[tid] = (m < cnt) ? g_tok[e * Tt + m] : -1;
    }
    __syncthreads();

    const bf16* APl[3];
    const bf16* BPl[3];
    if (FFN1) {
        APl[0] = g_xh;  APl[1] = g_xh;  APl[2] = g_xl;
        BPl[0] = g_w1h + (size_t)e * (size_t)Hh * Dd;
        BPl[1] = g_w1l + (size_t)e * (size_t)Hh * Dd;
        BPl[2] = BPl[0];
    } else {
        APl[0] = g_hh;  APl[1] = g_hh;  APl[2] = g_hl;
        BPl[0] = g_w2h + (size_t)e * (size_t)Dd * Hh;
        BPl[1] = g_w2l + (size_t)e * (size_t)Dd * Hh;
        BPl[2] = BPl[0];
    }

    auto load_stage = [&](int s, int st) {
        int seg = s / NCH;
        int k0  = (s - seg * NCH) * 64;
        const bf16* ap = APl[seg];
        const bf16* bp = BPl[seg];
        // A: 128 rows x 8 chunks = 1024 chunks, 4 per thread
        #pragma unroll
        for (int i = 0; i < 4; i++) {
            int idx = tid + i * 256;
            int row = idx >> 3, ch = idx & 7;
            uint32_t dst = sbase + SM_A(st) + sw_off(row, ch);
            const bf16* src;
            int sz = 16;
            if (FFN1) {
                int tok = toks[row];
                src = (tok >= 0) ? ap + (size_t)tok * KTOT + k0 + ch * 8 : ap;
                if (tok < 0) sz = 0;
            } else {
                int m = m0 + row;
                src = (m < cnt) ? ap + (size_t)(off + m) * KTOT + k0 + ch * 8 : ap;
                if (m >= cnt) sz = 0;
            }
            cp16(dst, src, sz);
        }
        // B: 256 rows x 8 chunks = 2048 chunks, 8 per thread
        #pragma unroll
        for (int i = 0; i < 8; i++) {
            int idx = tid + i * 256;
            int row = idx >> 3, ch = idx & 7;
            uint32_t dst = sbase + SM_B(st) + sw_off(row, ch);
            cp16(dst, bp + (size_t)(n0 + row) * KTOT + k0 + ch * 8, 16);
        }
        cp_commit();
    };

    float acc[2][16][4];
    #pragma unroll
    for (int i = 0; i < 2; i++)
        #pragma unroll
        for (int j = 0; j < 16; j++)
            #pragma unroll
            for (int q = 0; q < 4; q++) acc[i][j][q] = 0.0f;

    load_stage(0, 0);
    load_stage(1, 1);

    for (int s = 0; s < NSTG; s++) {
        int st = s % NSTAGE;
        cp_wait1();
        __syncthreads();                       // stage s ready; stage (s-1) consumed
        if (s + 2 < NSTG) load_stage(s + 2, (s + 2) % NSTAGE);

        uint32_t abase = sbase + SM_A(st);
        uint32_t bbase = sbase + SM_B(st);
        #pragma unroll
        for (int kk = 0; kk < 4; kk++) {
            uint32_t afr[2][4];
            #pragma unroll
            for (int i = 0; i < 2; i++) {
                int row = wr * 32 + i * 16 + (lid & 15);
                int ch  = kk * 2 + (lid >> 4);
                ldsm4(afr[i], abase + sw_off(row, ch));
            }
            #pragma unroll
            for (int j2 = 0; j2 < 8; j2++) {
                int row = wc * 128 + j2 * 16 + (lid & 7) + ((lid >> 4) << 3);
                int ch  = kk * 2 + ((lid >> 3) & 1);
                uint32_t r[4];
                ldsm4(r, bbase + sw_off(row, ch));
                mma16816(acc[0][j2 * 2],     afr[0], r);
                mma16816(acc[1][j2 * 2],     afr[1], r);
                mma16816(acc[0][j2 * 2 + 1], afr[0], r + 2);
                mma16816(acc[1][j2 * 2 + 1], afr[1], r + 2);
            }
        }
    }

    // -------- epilogue (register accumulators) ------------------------------
    #pragma unroll
    for (int i = 0; i < 2; i++) {
        #pragma unroll
        for (int rh = 0; rh < 2; rh++) {
            int m = m0 + wr * 32 + i * 16 + rh * 8 + (lid >> 2);
            if (m >= cnt) continue;
            #pragma unroll
            for (int j = 0; j < 16; j++) {
                int n = n0 + wc * 128 + j * 8 + (lid & 3) * 2;
                float v0 = acc[i][j][rh * 2 + 0];
                float v1 = acc[i][j][rh * 2 + 1];
                if (FFN1) {
                    const float* b1p = b1 + (size_t)e * Hh + n;
                    v0 = fmaxf(v0 + b1p[0], 0.f);
                    v1 = fmaxf(v1 + b1p[1], 0.f);
                    float h0 = __bfloat162float(__float2bfloat16(v0));
                    float h1 = __bfloat162float(__float2bfloat16(v1));
                    size_t base = (size_t)(off + m) * Hh + n;
                    *(unsigned*)(g_hh + base) = pack2(v0, v1);
                    *(unsigned*)(g_hl + base) = pack2(v0 - h0, v1 - h1);
                } else {
                    size_t base = (size_t)(off + m) * Dd + n;
                    *(float2*)(g_y + base) = make_float2(v0, v1);
                }
            }
        }
    }
}

// ---------------- combine: out[t] = g0*(y0+b2[e0]) + g1*(y1+b2[e1]) ----------
__global__ void combine_kernel(const float* __restrict__ b2,
                               float* __restrict__ out) {
    int t   = blockIdx.x;
    int tid = threadIdx.x;                    // 256 threads * float4 = 1024 = Dd
    int e0 = g_eidx[t * Kk + 0], e1 = g_eidx[t * Kk + 1];
    int s0 = g_off[e0] + g_pos[t * Kk + 0];
    int s1 = g_off[e1] + g_pos[t * Kk + 1];
    float g0 = g_gatev[t * Kk + 0], g1 = g_gatev[t * Kk + 1];

    const float4* y0 = (const float4*)(g_y + (size_t)s0 * Dd);
    const float4* y1 = (const float4*)(g_y + (size_t)s1 * Dd);
    const float4* c0 = (const float4*)(b2 + (size_t)e0 * Dd);
    const float4* c1 = (const float4*)(b2 + (size_t)e1 * Dd);
    float4* o = (float4*)(out + (size_t)t * Dd);

    float4 a = y0[tid], b = y1[tid], p = c0[tid], q = c1[tid];
    float4 r;
    r.x = g0 * (a.x + p.x) + g1 * (b.x + q.x);
    r.y = g0 * (a.y + p.y) + g1 * (b.y + q.y);
    r.z = g0 * (a.z + p.z) + g1 * (b.z + q.z);
    r.w = g0 * (a.w + p.w) + g1 * (b.w + q.w);
    o[tid] = r;
}

__global__ void ent_kernel(float* __restrict__ out, int out_size) {
    if (out_size > Tt * Dd)
        out[Tt * Dd] = g_ent / (float)Tt;
}

// ---------------- launch ------------------------------------------------------
extern "C" void kernel_launch(void* const* d_in, const int* in_sizes, int n_in,
                              void* d_out, int out_size) {
    const float* x  = (const float*)d_in[0];
    const float* wg = (const float*)d_in[1];
    const float* bg = (const float*)d_in[2];
    const float* w1 = (const float*)d_in[3];
    const float* b1 = (const float*)d_in[4];
    const float* w2 = (const float*)d_in[5];
    const float* b2 = (const float*)d_in[6];
    float* out = (float*)d_out;

    cudaFuncSetAttribute(moe_mma_kernel<true>,
                         cudaFuncAttributeMaxDynamicSharedMemorySize, MMA_SMEM_BYTES);
    cudaFuncSetAttribute(moe_mma_kernel<false>,
                         cudaFuncAttributeMaxDynamicSharedMemorySize, MMA_SMEM_BYTES);

    reset_kernel<<<1, 32>>>();
    gate_kernel<<<Tt / 8, 256>>>(x, wg, bg);
    offs_kernel<<<1, 32>>>();

    conv_x_kernel<<<(Tt * Dd / 4) / 256, 256>>>(x);
    conv_w1_kernel<<<dim3(Hh / 32, Dd / 32, Ee), dim3(32, 8)>>>(w1);
    conv_w2_kernel<<<dim3(Dd / 32, Hh / 32, Ee), dim3(32, 8)>>>(w2);

    moe_mma_kernel<true ><<<dim3(Hh / 256, Tt / 128, Ee), 256, MMA_SMEM_BYTES>>>(b1);
    moe_mma_kernel<false><<<dim3(Dd / 256, Tt / 128, Ee), 256, MMA_SMEM_BYTES>>>(b1);

    combine_kernel<<<Tt, 256>>>(b2, out);
    ent_kernel<<<1, 1>>>(out, out_size);
}

// round 10
// speedup vs baseline: 3.1595x; 1.1297x over previous
#include <cuda_runtime.h>
#include <cuda_bf16.h>
#include <math.h>
#include <stdint.h>

typedef __nv_bfloat16 bf16;

// Problem constants
#define Bb 2
#define Nn 2048
#define Dd 1024
#define Ee 8
#define Hh 2048
#define Kk 2
#define Tt (Bb*Nn)              // 4096 tokens
#define SLOTS (Tt*Kk)           // 8192 (token, expert) assignments

// ---------------- routing state ----------------------------------------------
__device__ int   g_count[Ee];
__device__ int   g_off[Ee];                   // exclusive prefix of counts
__device__ float g_ent;
__device__ int   g_tok[Ee * Tt];              // token id at (expert, pos)
__device__ int   g_pos[Tt * Kk];              // pos within expert bucket
__device__ int   g_eidx[Tt * Kk];             // expert id
__device__ float g_gatev[Tt * Kk];            // softmaxed gate

// ---------------- bf16 split planes ------------------------------------------
__device__ bf16  g_xh[(size_t)Tt * Dd],      g_xl[(size_t)Tt * Dd];
__device__ bf16  g_w1h[(size_t)Ee * Hh * Dd], g_w1l[(size_t)Ee * Hh * Dd]; // [E][H][D]
__device__ bf16  g_w2h[(size_t)Ee * Dd * Hh], g_w2l[(size_t)Ee * Dd * Hh]; // [E][D][H]
__device__ bf16  g_hh[(size_t)SLOTS * Hh],   g_hl[(size_t)SLOTS * Hh];     // hidden (compacted)
__device__ float g_y[(size_t)SLOTS * Dd];                                  // expert outputs

// ============================ PTX helpers ====================================
__device__ __forceinline__ uint32_t smem_u32(const void* p) {
    uint32_t a;
    asm("{ .reg .u64 t; cvta.to.shared.u64 t, %1; cvt.u32.u64 %0, t; }"
        : "=r"(a) : "l"(p));
    return a;
}
__device__ __forceinline__ void cp16(uint32_t dst, const void* src, int sz) {
    asm volatile("cp.async.cg.shared.global [%0], [%1], 16, %2;"
                 :: "r"(dst), "l"(src), "r"(sz) : "memory");
}
__device__ __forceinline__ void cp_commit() {
    asm volatile("cp.async.commit_group;" ::: "memory");
}
__device__ __forceinline__ void cp_wait1() {
    asm volatile("cp.async.wait_group 1;" ::: "memory");
}
__device__ __forceinline__ void cp_wait0() {
    asm volatile("cp.async.wait_group 0;" ::: "memory");
}
__device__ __forceinline__ void ldsm4(uint32_t* r, uint32_t addr) {
    asm volatile("ldmatrix.sync.aligned.m8n8.x4.shared.b16 {%0,%1,%2,%3}, [%4];"
                 : "=r"(r[0]), "=r"(r[1]), "=r"(r[2]), "=r"(r[3]) : "r"(addr));
}
__device__ __forceinline__ void mma16816(float* c, const uint32_t* a, const uint32_t* b) {
    asm volatile(
        "mma.sync.aligned.m16n8k16.row.col.f32.bf16.bf16.f32 "
        "{%0,%1,%2,%3}, {%4,%5,%6,%7}, {%8,%9}, {%0,%1,%2,%3};"
        : "+f"(c[0]), "+f"(c[1]), "+f"(c[2]), "+f"(c[3])
        : "r"(a[0]), "r"(a[1]), "r"(a[2]), "r"(a[3]), "r"(b[0]), "r"(b[1]));
}

// smem tile: rows x 8 chunks of 16B (64 bf16 per row), XOR-swizzled
__device__ __forceinline__ uint32_t sw_off(int row, int ch) {
    return (uint32_t)((row * 8 + (ch ^ (row & 7))) << 4);
}

// dynamic smem layout: per stage 96KB = AH 16K | AL 16K | BH 32K | BL 32K, 2 stages
#define SM_AH(st) (1024 + (st) * 98304)
#define SM_AL(st) (1024 + (st) * 98304 + 16384)
#define SM_BH(st) (1024 + (st) * 98304 + 32768)
#define SM_BL(st) (1024 + (st) * 98304 + 65536)
#define MMA_SMEM_BYTES (1024 + 2 * 98304)   // 197632

// ---------------- reset / offsets --------------------------------------------
__global__ void reset_kernel() {
    int i = threadIdx.x;
    if (i < Ee) g_count[i] = 0;
    if (i == 0) g_ent = 0.0f;
}
__global__ void offs_kernel() {
    if (threadIdx.x == 0) {
        int a = 0;
        #pragma unroll
        for (int e = 0; e < Ee; e++) { g_off[e] = a; a += g_count[e]; }
    }
}

// ---------------- gating: one warp per token ---------------------------------
__global__ void gate_kernel(const float* __restrict__ x,
                            const float* __restrict__ wg,
                            const float* __restrict__ bg) {
    int t    = (blockIdx.x * blockDim.x + threadIdx.x) >> 5;
    int lane = threadIdx.x & 31;
    if (t >= Tt) return;

    const float* xr = x + (size_t)t * Dd;
    float acc[Ee];
    #pragma unroll
    for (int e = 0; e < Ee; e++) acc[e] = 0.0f;

    for (int d = lane; d < Dd; d += 32) {
        float xv = xr[d];
        const float4* w4 = (const float4*)(wg + (size_t)d * Ee);
        float4 a = w4[0], b = w4[1];
        acc[0] += xv * a.x; acc[1] += xv * a.y; acc[2] += xv * a.z; acc[3] += xv * a.w;
        acc[4] += xv * b.x; acc[5] += xv * b.y; acc[6] += xv * b.z; acc[7] += xv * b.w;
    }
    #pragma unroll
    for (int e = 0; e < Ee; e++) {
        #pragma unroll
        for (int off = 16; off; off >>= 1)
            acc[e] += __shfl_xor_sync(0xffffffffu, acc[e], off);
    }

    if (lane == 0) {
        float best0 = -INFINITY, best1 = -INFINITY;
        int i0 = 0, i1 = 0;
        #pragma unroll
        for (int e = 0; e < Ee; e++) {
            float l = acc[e] + bg[e];
            if (l > best0)      { best1 = best0; i1 = i0; best0 = l; i0 = e; }
            else if (l > best1) { best1 = l; i1 = e; }
        }
        float ex = expf(best1 - best0);
        float g0 = 1.0f / (1.0f + ex);
        float g1 = ex * g0;
        float ent = -(g0 * logf(fmaxf(g0, 1e-8f)) + g1 * logf(fmaxf(g1, 1e-8f)));
        atomicAdd(&g_ent, ent);

        int p0 = atomicAdd(&g_count[i0], 1);
        g_tok[i0 * Tt + p0] = t;
        g_pos[t * Kk + 0]   = p0;
        g_gatev[t * Kk + 0] = g0;
        g_eidx[t * Kk + 0]  = i0;

        int p1 = atomicAdd(&g_count[i1], 1);
        g_tok[i1 * Tt + p1] = t;
        g_pos[t * Kk + 1]   = p1;
        g_gatev[t * Kk + 1] = g1;
        g_eidx[t * Kk + 1]  = i1;
    }
}

// ---------------- conversions ------------------------------------------------
__device__ __forceinline__ unsigned pack2(float a, float b) {
    bf16 ha = __float2bfloat16(a), hb = __float2bfloat16(b);
    return (unsigned)__bfloat16_as_ushort(ha)
         | ((unsigned)__bfloat16_as_ushort(hb) << 16);
}

__global__ void conv_x_kernel(const float* __restrict__ x) {
    int i = blockIdx.x * blockDim.x + threadIdx.x;       // Tt*Dd/4 threads
    float4 v = ((const float4*)x)[i];
    float hx = __bfloat162float(__float2bfloat16(v.x));
    float hy = __bfloat162float(__float2bfloat16(v.y));
    float hz = __bfloat162float(__float2bfloat16(v.z));
    float hw = __bfloat162float(__float2bfloat16(v.w));
    ((uint2*)g_xh)[i] = make_uint2(pack2(v.x, v.y), pack2(v.z, v.w));
    ((uint2*)g_xl)[i] = make_uint2(pack2(v.x - hx, v.y - hy), pack2(v.z - hz, v.w - hw));
}

// transpose + split:  in [E][R][C] -> out [E][C][R]  (vectorized 4B writes)
__device__ __forceinline__ void transpose_conv_body(
    const float* __restrict__ in, bf16* __restrict__ oh, bf16* __restrict__ ol,
    int R, int C) {
    __shared__ float ts[32][33];
    int e  = blockIdx.z;
    int r0 = blockIdx.y * 32, c0 = blockIdx.x * 32;
    int tx = threadIdx.x, ty = threadIdx.y;
    const float* ip = in + (size_t)e * R * C;
    #pragma unroll
    for (int i = 0; i < 4; i++)
        ts[ty + 8 * i][tx] = ip[(size_t)(r0 + ty + 8 * i) * C + (c0 + tx)];
    __syncthreads();
    int id = ty * 32 + tx;
    int r2 = id & 15;                 // output row pair (covers 32 rows)
    int cb = id >> 4;                 // 0..15
    unsigned* ohp = (unsigned*)(oh + (size_t)e * C * R);
    unsigned* olp = (unsigned*)(ol + (size_t)e * C * R);
    #pragma unroll
    for (int p = 0; p < 2; p++) {
        int c = cb + p * 16;
        float v0 = ts[2 * r2][c], v1 = ts[2 * r2 + 1][c];
        float h0 = __bfloat162float(__float2bfloat16(v0));
        float h1 = __bfloat162float(__float2bfloat16(v1));
        size_t o = (((size_t)(c0 + c) * R + r0) >> 1) + r2;
        ohp[o] = pack2(v0, v1);
        olp[o] = pack2(v0 - h0, v1 - h1);
    }
}
__global__ void conv_w1_kernel(const float* __restrict__ w1) {
    transpose_conv_body(w1, g_w1h, g_w1l, Dd, Hh);
}
__global__ void conv_w2_kernel(const float* __restrict__ w2) {
    transpose_conv_body(w2, g_w2h, g_w2l, Hh, Dd);
}

// ---------------- HMMA GEMM: 128x256 tile, BK=64, fused hi/lo planes ---------
// One stage per K-chunk loads Ah, Al, Bh, Bl; MMA does Ah*Bh + Ah*Bl + Al*Bh
// into the same fp32 accumulators (lo*lo dropped, ~2^-18). 2-stage pipeline.
// FFN1: C[cnt,H] = Xg[cnt,D] @ W1t[H,D]^T  (+b1, relu -> bf16 hi/lo planes)
// FFN2: C[cnt,D] = H [cnt,H] @ W2t[D,H]^T  (-> fp32 y)
// 8 warps, warp tile 32(m) x 128(n).
template <bool FFN1>
__global__ __launch_bounds__(256, 1)
void moe_mma_kernel(const float* __restrict__ b1) {
    constexpr int KTOT = FFN1 ? Dd : Hh;
    constexpr int NCH  = KTOT / 64;

    int e   = blockIdx.z;
    int cnt = g_count[e];
    int m0  = blockIdx.y * 128;
    if (m0 >= cnt) return;
    int n0  = blockIdx.x * 256;
    int off = g_off[e];

    extern __shared__ __align__(1024) char smem[];
    uint32_t sbase = smem_u32(smem);
    int tid = threadIdx.x, wid = tid >> 5, lid = tid & 31;
    int wr = wid & 3, wc = wid >> 2;          // warp tile: rows wr*32, cols wc*128

    int* toks = (int*)smem;
    if (FFN1 && tid < 128) {
        int m = m0 + tid;
        toks[tid] = (m < cnt) ? g_tok[e * Tt + m] : -1;
    }
    __syncthreads();

    const bf16* aph; const bf16* apl;
    const bf16* bph; const bf16* bpl;
    if (FFN1) {
        aph = g_xh;  apl = g_xl;
        bph = g_w1h + (size_t)e * (size_t)Hh * Dd;
        bpl = g_w1l + (size_t)e * (size_t)Hh * Dd;
    } else {
        aph = g_hh;  apl = g_hl;
        bph = g_w2h + (size_t)e * (size_t)Dd * Hh;
        bpl = g_w2l + (size_t)e * (size_t)Dd * Hh;
    }

    auto load_stage = [&](int s, int st) {
        int k0 = s * 64;
        // A planes: 128 rows x 8 chunks = 1024 chunks each, 4/thread
        #pragma unroll
        for (int i = 0; i < 4; i++) {
            int idx = tid + i * 256;
            int row = idx >> 3, ch = idx & 7;
            int sz = 16;
            size_t goff;
            if (FFN1) {
                int tok = toks[row];
                if (tok < 0) { sz = 0; tok = 0; }
                goff = (size_t)tok * KTOT + k0 + ch * 8;
            } else {
                int m = m0 + row;
                if (m >= cnt) { sz = 0; m = 0; }
                goff = (size_t)(off + m) * KTOT + k0 + ch * 8;
            }
            uint32_t so = sw_off(row, ch);
            cp16(sbase + SM_AH(st) + so, aph + goff, sz);
            cp16(sbase + SM_AL(st) + so, apl + goff, sz);
        }
        // B planes: 256 rows x 8 chunks = 2048 chunks each, 8/thread
        #pragma unroll
        for (int i = 0; i < 8; i++) {
            int idx = tid + i * 256;
            int row = idx >> 3, ch = idx & 7;
            size_t goff = (size_t)(n0 + row) * KTOT + k0 + ch * 8;
            uint32_t so = sw_off(row, ch);
            cp16(sbase + SM_BH(st) + so, bph + goff, 16);
            cp16(sbase + SM_BL(st) + so, bpl + goff, 16);
        }
        cp_commit();
    };

    float acc[2][16][4];
    #pragma unroll
    for (int i = 0; i < 2; i++)
        #pragma unroll
        for (int j = 0; j < 16; j++)
            #pragma unroll
            for (int q = 0; q < 4; q++) acc[i][j][q] = 0.0f;

    load_stage(0, 0);

    for (int s = 0; s < NCH; s++) {
        int st = s & 1;
        if (s + 1 < NCH) { load_stage(s + 1, st ^ 1); cp_wait1(); }
        else             { cp_wait0(); }
        __syncthreads();

        uint32_t aH = sbase + SM_AH(st), aL = sbase + SM_AL(st);
        uint32_t bH = sbase + SM_BH(st), bL = sbase + SM_BL(st);
        #pragma unroll
        for (int kk = 0; kk < 4; kk++) {
            uint32_t ah[2][4], al[2][4];
            #pragma unroll
            for (int i = 0; i < 2; i++) {
                int row = wr * 32 + i * 16 + (lid & 15);
                int ch  = kk * 2 + (lid >> 4);
                uint32_t so = sw_off(row, ch);
                ldsm4(ah[i], aH + so);
                ldsm4(al[i], aL + so);
            }
            #pragma unroll
            for (int j2 = 0; j2 < 8; j2++) {
                int row = wc * 128 + j2 * 16 + (lid & 7) + ((lid >> 4) << 3);
                int ch  = kk * 2 + ((lid >> 3) & 1);
                uint32_t so = sw_off(row, ch);
                uint32_t bh[4];
                ldsm4(bh, bH + so);
                mma16816(acc[0][j2 * 2],     ah[0], bh);
                mma16816(acc[1][j2 * 2],     ah[1], bh);
                mma16816(acc[0][j2 * 2 + 1], ah[0], bh + 2);
                mma16816(acc[1][j2 * 2 + 1], ah[1], bh + 2);
                mma16816(acc[0][j2 * 2],     al[0], bh);
                mma16816(acc[1][j2 * 2],     al[1], bh);
                mma16816(acc[0][j2 * 2 + 1], al[0], bh + 2);
                mma16816(acc[1][j2 * 2 + 1], al[1], bh + 2);
                uint32_t bl[4];
                ldsm4(bl, bL + so);
                mma16816(acc[0][j2 * 2],     ah[0], bl);
                mma16816(acc[1][j2 * 2],     ah[1], bl);
                mma16816(acc[0][j2 * 2 + 1], ah[0], bl + 2);
                mma16816(acc[1][j2 * 2 + 1], ah[1], bl + 2);
            }
        }
        __syncthreads();                       // all warps done with buf st
    }

    // -------- epilogue (register accumulators) ------------------------------
    #pragma unroll
    for (int i = 0; i < 2; i++) {
        #pragma unroll
        for (int rh = 0; rh < 2; rh++) {
            int m = m0 + wr * 32 + i * 16 + rh * 8 + (lid >> 2);
            if (m >= cnt) continue;
            #pragma unroll
            for (int j = 0; j < 16; j++) {
                int n = n0 + wc * 128 + j * 8 + (lid & 3) * 2;
                float v0 = acc[i][j][rh * 2 + 0];
                float v1 = acc[i][j][rh * 2 + 1];
                if (FFN1) {
                    const float* b1p = b1 + (size_t)e * Hh + n;
                    v0 = fmaxf(v0 + b1p[0], 0.f);
                    v1 = fmaxf(v1 + b1p[1], 0.f);
                    float h0 = __bfloat162float(__float2bfloat16(v0));
                    float h1 = __bfloat162float(__float2bfloat16(v1));
                    size_t base = (size_t)(off + m) * Hh + n;
                    *(unsigned*)(g_hh + base) = pack2(v0, v1);
                    *(unsigned*)(g_hl + base) = pack2(v0 - h0, v1 - h1);
                } else {
                    size_t base = (size_t)(off + m) * Dd + n;
                    *(float2*)(g_y + base) = make_float2(v0, v1);
                }
            }
        }
    }
}

// ---------------- combine: out[t] = g0*(y0+b2[e0]) + g1*(y1+b2[e1]) ----------
__global__ void combine_kernel(const float* __restrict__ b2,
                               float* __restrict__ out) {
    int t   = blockIdx.x;
    int tid = threadIdx.x;                    // 256 threads * float4 = 1024 = Dd
    int e0 = g_eidx[t * Kk + 0], e1 = g_eidx[t * Kk + 1];
    int s0 = g_off[e0] + g_pos[t * Kk + 0];
    int s1 = g_off[e1] + g_pos[t * Kk + 1];
    float g0 = g_gatev[t * Kk + 0], g1 = g_gatev[t * Kk + 1];

    const float4* y0 = (const float4*)(g_y + (size_t)s0 * Dd);
    const float4* y1 = (const float4*)(g_y + (size_t)s1 * Dd);
    const float4* c0 = (const float4*)(b2 + (size_t)e0 * Dd);
    const float4* c1 = (const float4*)(b2 + (size_t)e1 * Dd);
    float4* o = (float4*)(out + (size_t)t * Dd);

    float4 a = y0[tid], b = y1[tid], p = c0[tid], q = c1[tid];
    float4 r;
    r.x = g0 * (a.x + p.x) + g1 * (b.x + q.x);
    r.y = g0 * (a.y + p.y) + g1 * (b.y + q.y);
    r.z = g0 * (a.z + p.z) + g1 * (b.z + q.z);
    r.w = g0 * (a.w + p.w) + g1 * (b.w + q.w);
    o[tid] = r;
}

__global__ void ent_kernel(float* __restrict__ out, int out_size) {
    if (out_size > Tt * Dd)
        out[Tt * Dd] = g_ent / (float)Tt;
}

// ---------------- launch ------------------------------------------------------
extern "C" void kernel_launch(void* const* d_in, const int* in_sizes, int n_in,
                              void* d_out, int out_size) {
    const float* x  = (const float*)d_in[0];
    const float* wg = (const float*)d_in[1];
    const float* bg = (const float*)d_in[2];
    const float* w1 = (const float*)d_in[3];
    const float* b1 = (const float*)d_in[4];
    const float* w2 = (const float*)d_in[5];
    const float* b2 = (const float*)d_in[6];
    float* out = (float*)d_out;

    cudaFuncSetAttribute(moe_mma_kernel<true>,
                         cudaFuncAttributeMaxDynamicSharedMemorySize, MMA_SMEM_BYTES);
    cudaFuncSetAttribute(moe_mma_kernel<false>,
                         cudaFuncAttributeMaxDynamicSharedMemorySize, MMA_SMEM_BYTES);

    reset_kernel<<<1, 32>>>();
    gate_kernel<<<Tt / 8, 256>>>(x, wg, bg);
    offs_kernel<<<1, 32>>>();

    conv_x_kernel<<<(Tt * Dd / 4) / 256, 256>>>(x);
    conv_w1_kernel<<<dim3(Hh / 32, Dd / 32, Ee), dim3(32, 8)>>>(w1);
    conv_w2_kernel<<<dim3(Dd / 32, Hh / 32, Ee), dim3(32, 8)>>>(w2);

    moe_mma_kernel<true ><<<dim3(Hh / 256, Tt / 128, Ee), 256, MMA_SMEM_BYTES>>>(b1);
    moe_mma_kernel<false><<<dim3(Dd / 256, Tt / 128, Ee), 256, MMA_SMEM_BYTES>>>(b1);

    combine_kernel<<<Tt, 256>>>(b2, out);
    ent_kernel<<<1, 1>>>(out, out_size);
}